// round 11
// baseline (speedup 1.0000x reference)
#include <cuda_runtime.h>
#include <cstdint>

// Problem constants
#define NSEG 513
#define NBATCH 8
#define HW (1024 * 1024)

#define BLOCKS_PER_BATCH 64
#define THREADS 512
#define PIX_PER_BLOCK (HW / BLOCKS_PER_BATCH)      // 16384
#define VEC_ITERS (PIX_PER_BLOCK / (THREADS * 4))  // 8  (same as proven hot loop)

// Fixed-point packing: [count:12 | clean_q14:26 | pred_q14:26]
#define Q_SCALE 16384.0f
#define FIELD_MASK 0x3FFFFFFull
#define CNT_SHIFT 52
#define CLEAN_SHIFT 26

// Global scratch — zero-initialized at module load; each invocation restores all
// of it to zero before finishing (elected blocks zero g_hist + tickets, the
// combine kernel zeroes g_partial), so the correctness run and every graph
// replay observe zeros on entry. Deterministic, allocation-free.
__device__ unsigned long long g_hist[NBATCH * NSEG];
__device__ unsigned int g_ticket[NBATCH];
__device__ float g_partial[NBATCH][6];

__device__ __forceinline__ unsigned long long pack_pix(float c, float p) {
    unsigned int ci = __float2uint_rn(c * Q_SCALE);
    unsigned int pi = __float2uint_rn(p * Q_SCALE);
    return (unsigned long long)ci * (1ull << CLEAN_SHIFT) +
           ((1ull << CNT_SHIFT) + (unsigned long long)pi);
}

// 4 blocks/SM x 512 threads = 2048 resident threads/SM (same as R9's 8x256),
// 32-reg cap unchanged. Halves per-block overheads: smem zero-init and the
// 513-slot global flush (262K vs 525K L2 atomics).
__global__ __launch_bounds__(THREADS, 4)
void hist_kernel(const float* __restrict__ clean,
                 const float* __restrict__ pred,
                 const int* __restrict__ ids) {
    __shared__ unsigned long long sh[NSEG];
    __shared__ int s_is_last;
    __shared__ float sbuf[16][8];

    const int tid = threadIdx.x;
    for (int i = tid; i < NSEG; i += THREADS) sh[i] = 0ull;
    __syncthreads();

    // ---------------- histogram phase ----------------
    const int b = blockIdx.y;
    const size_t base = (size_t)b * HW + (size_t)blockIdx.x * PIX_PER_BLOCK;
    const float4* __restrict__ c4 = (const float4*)(clean + base);
    const float4* __restrict__ p4 = (const float4*)(pred + base);
    const int4* __restrict__ i4 = (const int4*)(ids + base);

#pragma unroll
    for (int it = 0; it < VEC_ITERS; ++it) {
        const int idx = it * THREADS + tid;
        const float4 c = c4[idx];
        const float4 p = p4[idx];
        const int4 id = i4[idx];
        atomicAdd(&sh[id.x], pack_pix(c.x, p.x));
        atomicAdd(&sh[id.y], pack_pix(c.y, p.y));
        atomicAdd(&sh[id.z], pack_pix(c.z, p.z));
        atomicAdd(&sh[id.w], pack_pix(c.w, p.w));
    }
    __syncthreads();

    unsigned long long* gh = g_hist + (size_t)b * NSEG;
    for (int i = tid; i < NSEG; i += THREADS) {
        unsigned long long v = sh[i];
        if (v) atomicAdd(&gh[i], v);
    }
    __syncthreads();

    // ---------------- per-batch last-block election ----------------
    if (tid == 0) {
        __threadfence();
        unsigned int old = atomicAdd(&g_ticket[b], 1u);
        s_is_last = (old == BLOCKS_PER_BATCH - 1) ? 1 : 0;
    }
    __syncthreads();
    if (!s_is_last) return;
    __threadfence();

    // ------- per-batch reduction tail (8 elected blocks run in parallel) ----
    // 512 threads: thread t handles segment 1+t (segments 1..512).
    const int lane = tid & 31;
    const int warp = tid >> 5;

    float acc[8];
#pragma unroll
    for (int q = 0; q < 8; ++q) acc[q] = 0.f;

    {
        const int seg = 1 + tid;
        const unsigned long long v = __ldcg(&gh[seg]);

        const float cntf = (float)(unsigned int)(v >> CNT_SHIFT);
        const float inv = 1.0f / fmaxf(cntf, 1.0f);
        const float cm =
            (float)(unsigned int)((v >> CLEAN_SHIFT) & FIELD_MASK) * (1.0f / Q_SCALE) * inv;
        const float pm =
            (float)(unsigned int)(v & FIELD_MASK) * (1.0f / Q_SCALE) * inv;

        const bool valid = cntf >= 8.0f;
        const bool tumor = valid && (cm >= 0.7f);
        const bool normal = valid && (cm <= 0.3f);
        const bool enh = tumor || normal;
        const bool pres = valid && !enh;

        float target = cm;
        if (tumor) target = fminf(cm + 0.08f, 1.0f);
        if (normal) target = fmaxf(cm - 0.08f, 0.0f);
        const float d = pm - target;
        const float ad = fabsf(d);
        const float sl = (ad < 1.0f) ? 0.5f * d * d : ad - 0.5f;

        const bool tm = valid && (pm > 0.5f);
        const bool nm = valid && !(pm > 0.5f);

        acc[0] = enh ? sl : 0.f;
        acc[1] = enh ? 1.f : 0.f;
        acc[2] = pres ? sl : 0.f;
        acc[3] = pres ? 1.f : 0.f;
        acc[4] = tm ? pm : 0.f;
        acc[5] = tm ? 1.f : 0.f;
        acc[6] = nm ? pm : 0.f;
        acc[7] = nm ? 1.f : 0.f;
    }

#pragma unroll
    for (int q = 0; q < 8; ++q) {
        float x = acc[q];
#pragma unroll
        for (int o = 16; o > 0; o >>= 1) x += __shfl_down_sync(0xffffffffu, x, o);
        if (lane == 0) sbuf[warp][q] = x;
    }
    __syncthreads();

    // zero this batch's hist slice for the next invocation (overlaps tid0 work)
    for (int i = tid; i < NSEG; i += THREADS) gh[i] = 0ull;

    if (tid == 0) {
        float r[8];
#pragma unroll
        for (int q = 0; q < 8; ++q) r[q] = 0.f;
        for (int w = 0; w < 16; ++w)
#pragma unroll
            for (int q = 0; q < 8; ++q) r[q] += sbuf[w][q];

        const float loss_enh = r[0] / fmaxf(r[1], 1.0f);
        const float loss_pres = r[2] / fmaxf(r[3], 1.0f);
        const float has_e = (r[1] > 0.f) ? 1.f : 0.f;
        const float has_p = (r[3] > 0.f) ? 1.f : 0.f;
        const float cnt = has_e + has_p;
        const float loss_b =
            (loss_enh * has_e + 0.5f * loss_pres * has_p) / fmaxf(cnt, 1.0f);
        const float valid_b = (cnt > 0.f) ? 1.f : 0.f;

        const float has_t = (r[5] > 0.f) ? 1.f : 0.f;
        const float t_term = (r[4] / fmaxf(r[5], 1.0f)) * has_t;
        const float has_n = (r[7] > 0.f) ? 1.f : 0.f;
        const float n_term = (r[6] / fmaxf(r[7], 1.0f)) * has_n;

        g_partial[b][0] = loss_b * valid_b;
        g_partial[b][1] = valid_b;
        g_partial[b][2] = t_term;
        g_partial[b][3] = has_t;
        g_partial[b][4] = n_term;
        g_partial[b][5] = has_n;

        g_ticket[b] = 0u;
    }
}

// One warp: lane l < 8 combines batch l's partials; shuffle-reduce; write out.
__global__ __launch_bounds__(32)
void combine_kernel(float* __restrict__ out) {
    const int lane = threadIdx.x;

    float loss_term = 0.f, valid_b = 0.f, t_term = 0.f, has_t = 0.f,
          n_term = 0.f, has_n = 0.f;
    if (lane < 8) {
        loss_term = __ldcg(&g_partial[lane][0]);
        valid_b = __ldcg(&g_partial[lane][1]);
        t_term = __ldcg(&g_partial[lane][2]);
        has_t = __ldcg(&g_partial[lane][3]);
        n_term = __ldcg(&g_partial[lane][4]);
        has_n = __ldcg(&g_partial[lane][5]);
    }

#pragma unroll
    for (int o = 4; o > 0; o >>= 1) {
        loss_term += __shfl_down_sync(0xffffffffu, loss_term, o);
        valid_b += __shfl_down_sync(0xffffffffu, valid_b, o);
        t_term += __shfl_down_sync(0xffffffffu, t_term, o);
        has_t += __shfl_down_sync(0xffffffffu, has_t, o);
        n_term += __shfl_down_sync(0xffffffffu, n_term, o);
        has_n += __shfl_down_sync(0xffffffffu, has_n, o);
    }

    if (lane == 0) {
        float loss_prob = loss_term / fmaxf(valid_b, 1.0f);
        float avg_t = (has_t > 0.f) ? (t_term / fmaxf(has_t, 1.0f)) : -1.0f;
        float avg_n = (has_n > 0.f) ? (n_term / fmaxf(has_n, 1.0f)) : -1.0f;
        if (!(valid_b > 0.f)) {
            loss_prob = 0.0f;
            avg_t = -1.0f;
            avg_n = -1.0f;
        }
        out[0] = loss_prob;
        out[1] = 0.0f;
        out[2] = avg_t;
        out[3] = avg_n;
    }

    // re-zero g_partial (48 floats) for the next invocation
    float* gp = &g_partial[0][0];
    for (int i = lane; i < NBATCH * 6; i += 32) gp[i] = 0.f;
}

extern "C" void kernel_launch(void* const* d_in, const int* in_sizes, int n_in,
                              void* d_out, int out_size) {
    const float* clean = (const float*)d_in[0];
    const float* pred = (const float*)d_in[1];
    const int* ids = (const int*)d_in[2];
    float* out = (float*)d_out;

    dim3 grid(BLOCKS_PER_BATCH, NBATCH);
    hist_kernel<<<grid, THREADS>>>(clean, pred, ids);
    combine_kernel<<<1, 32>>>(out);
}

// round 14
// speedup vs baseline: 1.1039x; 1.1039x over previous
#include <cuda_runtime.h>
#include <cstdint>

// Problem constants
#define NSEG 513
#define NBATCH 8
#define HW (1024 * 1024)

#define BLOCKS_PER_BATCH 256
#define THREADS 128
#define PIX_PER_BLOCK (HW / BLOCKS_PER_BATCH)      // 4096
#define VEC_ITERS (PIX_PER_BLOCK / (THREADS * 4))  // 8  (identical hot loop shape)

// Fixed-point packing: [count:12 | clean_q14:26 | pred_q14:26]
#define Q_SCALE 16384.0f
#define FIELD_MASK 0x3FFFFFFull
#define CNT_SHIFT 52
#define CLEAN_SHIFT 26

// Global scratch — zero-initialized at module load; each invocation restores all
// of it to zero before finishing (elected blocks zero g_hist + tickets, the
// combine kernel zeroes g_partial), so the correctness run and every graph
// replay observe zeros on entry. Deterministic, allocation-free.
__device__ unsigned long long g_hist[NBATCH * NSEG];
__device__ unsigned int g_ticket[NBATCH];
__device__ float g_partial[NBATCH][6];

__device__ __forceinline__ unsigned long long pack_pix(float c, float p) {
    unsigned int ci = __float2uint_rn(c * Q_SCALE);
    unsigned int pi = __float2uint_rn(p * Q_SCALE);
    return (unsigned long long)ci * (1ull << CLEAN_SHIFT) +
           ((1ull << CNT_SHIFT) + (unsigned long long)pi);
}

// 16 blocks/SM x 128 threads = 2048 resident threads/SM (same as R9's 8x256)
// but SIXTEEN shared-histogram copies per SM -> half the per-copy same-address
// atomic serialization (the R9-vs-R11 delta showed copies/SM is the dominant
// knob: 8->4 copies cost ~8us at equal occupancy).
__global__ __launch_bounds__(THREADS, 16)
void hist_kernel(const float* __restrict__ clean,
                 const float* __restrict__ pred,
                 const int* __restrict__ ids) {
    __shared__ unsigned long long sh[NSEG];
    __shared__ int s_is_last;
    __shared__ float sbuf[4][8];

    const int tid = threadIdx.x;
    for (int i = tid; i < NSEG; i += THREADS) sh[i] = 0ull;
    __syncthreads();

    // ---------------- histogram phase ----------------
    const int b = blockIdx.y;
    const size_t base = (size_t)b * HW + (size_t)blockIdx.x * PIX_PER_BLOCK;
    const float4* __restrict__ c4 = (const float4*)(clean + base);
    const float4* __restrict__ p4 = (const float4*)(pred + base);
    const int4* __restrict__ i4 = (const int4*)(ids + base);

#pragma unroll
    for (int it = 0; it < VEC_ITERS; ++it) {
        const int idx = it * THREADS + tid;
        const float4 c = c4[idx];
        const float4 p = p4[idx];
        const int4 id = i4[idx];
        atomicAdd(&sh[id.x], pack_pix(c.x, p.x));
        atomicAdd(&sh[id.y], pack_pix(c.y, p.y));
        atomicAdd(&sh[id.z], pack_pix(c.z, p.z));
        atomicAdd(&sh[id.w], pack_pix(c.w, p.w));
    }
    __syncthreads();

    unsigned long long* gh = g_hist + (size_t)b * NSEG;
    for (int i = tid; i < NSEG; i += THREADS) {
        unsigned long long v = sh[i];
        if (v) atomicAdd(&gh[i], v);
    }
    __syncthreads();

    // ---------------- per-batch last-block election ----------------
    if (tid == 0) {
        __threadfence();
        unsigned int old = atomicAdd(&g_ticket[b], 1u);
        s_is_last = (old == BLOCKS_PER_BATCH - 1) ? 1 : 0;
    }
    __syncthreads();
    if (!s_is_last) return;
    __threadfence();

    // ------- per-batch reduction tail (8 elected blocks run in parallel) ----
    // 128 threads: thread t handles segments 1+t, 1+t+128, 1+t+256, 1+t+384.
    const int lane = tid & 31;
    const int warp = tid >> 5;

    float acc[8];
#pragma unroll
    for (int q = 0; q < 8; ++q) acc[q] = 0.f;

#pragma unroll
    for (int it = 0; it < 4; ++it) {
        const int seg = 1 + it * 128 + tid;
        const unsigned long long v = __ldcg(&gh[seg]);

        const float cntf = (float)(unsigned int)(v >> CNT_SHIFT);
        const float inv = 1.0f / fmaxf(cntf, 1.0f);
        const float cm =
            (float)(unsigned int)((v >> CLEAN_SHIFT) & FIELD_MASK) * (1.0f / Q_SCALE) * inv;
        const float pm =
            (float)(unsigned int)(v & FIELD_MASK) * (1.0f / Q_SCALE) * inv;

        const bool valid = cntf >= 8.0f;
        const bool tumor = valid && (cm >= 0.7f);
        const bool normal = valid && (cm <= 0.3f);
        const bool enh = tumor || normal;
        const bool pres = valid && !enh;

        float target = cm;
        if (tumor) target = fminf(cm + 0.08f, 1.0f);
        if (normal) target = fmaxf(cm - 0.08f, 0.0f);
        const float d = pm - target;
        const float ad = fabsf(d);
        const float sl = (ad < 1.0f) ? 0.5f * d * d : ad - 0.5f;

        const bool tm = valid && (pm > 0.5f);
        const bool nm = valid && !(pm > 0.5f);

        acc[0] += enh ? sl : 0.f;
        acc[1] += enh ? 1.f : 0.f;
        acc[2] += pres ? sl : 0.f;
        acc[3] += pres ? 1.f : 0.f;
        acc[4] += tm ? pm : 0.f;
        acc[5] += tm ? 1.f : 0.f;
        acc[6] += nm ? pm : 0.f;
        acc[7] += nm ? 1.f : 0.f;
    }

#pragma unroll
    for (int q = 0; q < 8; ++q) {
        float x = acc[q];
#pragma unroll
        for (int o = 16; o > 0; o >>= 1) x += __shfl_down_sync(0xffffffffu, x, o);
        if (lane == 0) sbuf[warp][q] = x;
    }
    __syncthreads();

    // zero this batch's hist slice for the next invocation (overlaps tid0 work)
    for (int i = tid; i < NSEG; i += THREADS) gh[i] = 0ull;

    if (tid == 0) {
        float r[8];
#pragma unroll
        for (int q = 0; q < 8; ++q) r[q] = 0.f;
        for (int w = 0; w < 4; ++w)
#pragma unroll
            for (int q = 0; q < 8; ++q) r[q] += sbuf[w][q];

        const float loss_enh = r[0] / fmaxf(r[1], 1.0f);
        const float loss_pres = r[2] / fmaxf(r[3], 1.0f);
        const float has_e = (r[1] > 0.f) ? 1.f : 0.f;
        const float has_p = (r[3] > 0.f) ? 1.f : 0.f;
        const float cnt = has_e + has_p;
        const float loss_b =
            (loss_enh * has_e + 0.5f * loss_pres * has_p) / fmaxf(cnt, 1.0f);
        const float valid_b = (cnt > 0.f) ? 1.f : 0.f;

        const float has_t = (r[5] > 0.f) ? 1.f : 0.f;
        const float t_term = (r[4] / fmaxf(r[5], 1.0f)) * has_t;
        const float has_n = (r[7] > 0.f) ? 1.f : 0.f;
        const float n_term = (r[6] / fmaxf(r[7], 1.0f)) * has_n;

        g_partial[b][0] = loss_b * valid_b;
        g_partial[b][1] = valid_b;
        g_partial[b][2] = t_term;
        g_partial[b][3] = has_t;
        g_partial[b][4] = n_term;
        g_partial[b][5] = has_n;

        g_ticket[b] = 0u;
    }
}

// One warp: lane l < 8 combines batch l's partials; shuffle-reduce; write out.
__global__ __launch_bounds__(32)
void combine_kernel(float* __restrict__ out) {
    const int lane = threadIdx.x;

    float loss_term = 0.f, valid_b = 0.f, t_term = 0.f, has_t = 0.f,
          n_term = 0.f, has_n = 0.f;
    if (lane < 8) {
        loss_term = __ldcg(&g_partial[lane][0]);
        valid_b = __ldcg(&g_partial[lane][1]);
        t_term = __ldcg(&g_partial[lane][2]);
        has_t = __ldcg(&g_partial[lane][3]);
        n_term = __ldcg(&g_partial[lane][4]);
        has_n = __ldcg(&g_partial[lane][5]);
    }

#pragma unroll
    for (int o = 4; o > 0; o >>= 1) {
        loss_term += __shfl_down_sync(0xffffffffu, loss_term, o);
        valid_b += __shfl_down_sync(0xffffffffu, valid_b, o);
        t_term += __shfl_down_sync(0xffffffffu, t_term, o);
        has_t += __shfl_down_sync(0xffffffffu, has_t, o);
        n_term += __shfl_down_sync(0xffffffffu, n_term, o);
        has_n += __shfl_down_sync(0xffffffffu, has_n, o);
    }

    if (lane == 0) {
        float loss_prob = loss_term / fmaxf(valid_b, 1.0f);
        float avg_t = (has_t > 0.f) ? (t_term / fmaxf(has_t, 1.0f)) : -1.0f;
        float avg_n = (has_n > 0.f) ? (n_term / fmaxf(has_n, 1.0f)) : -1.0f;
        if (!(valid_b > 0.f)) {
            loss_prob = 0.0f;
            avg_t = -1.0f;
            avg_n = -1.0f;
        }
        out[0] = loss_prob;
        out[1] = 0.0f;
        out[2] = avg_t;
        out[3] = avg_n;
    }

    // re-zero g_partial (48 floats) for the next invocation
    float* gp = &g_partial[0][0];
    for (int i = lane; i < NBATCH * 6; i += 32) gp[i] = 0.f;
}

extern "C" void kernel_launch(void* const* d_in, const int* in_sizes, int n_in,
                              void* d_out, int out_size) {
    const float* clean = (const float*)d_in[0];
    const float* pred = (const float*)d_in[1];
    const int* ids = (const int*)d_in[2];
    float* out = (float*)d_out;

    dim3 grid(BLOCKS_PER_BATCH, NBATCH);
    hist_kernel<<<grid, THREADS>>>(clean, pred, ids);
    combine_kernel<<<1, 32>>>(out);
}

// round 16
// speedup vs baseline: 1.2241x; 1.1089x over previous
#include <cuda_runtime.h>
#include <cstdint>

// Problem constants
#define NSEG 513
#define NBATCH 8
#define HW (1024 * 1024)

#define BLOCKS_PER_BATCH 128
#define THREADS 256
#define PIX_PER_BLOCK (HW / BLOCKS_PER_BATCH)      // 8192
#define VEC_ITERS (PIX_PER_BLOCK / (THREADS * 4))  // 8

// Fixed-point packing: [count:12 | clean_q14:26 | pred_q14:26]
#define Q_SCALE 16384.0f
#define FIELD_MASK 0x3FFFFFFull
#define CNT_SHIFT 52
#define CLEAN_SHIFT 26

// Global scratch — zero-initialized at module load; each invocation restores all
// of it to zero before finishing (elected blocks zero g_hist + tickets, the
// combine kernel zeroes g_partial), so the correctness run and every graph
// replay observe zeros on entry. Deterministic, allocation-free.
__device__ unsigned long long g_hist[NBATCH * NSEG];
__device__ unsigned int g_ticket[NBATCH];
__device__ float g_partial[NBATCH][6];

__device__ __forceinline__ unsigned long long pack_pix(float c, float p) {
    unsigned int ci = __float2uint_rn(c * Q_SCALE);
    unsigned int pi = __float2uint_rn(p * Q_SCALE);
    return (unsigned long long)ci * (1ull << CLEAN_SHIFT) +
           ((1ull << CNT_SHIFT) + (unsigned long long)pi);
}

// R9 geometry exactly (8 blocks/SM x 256 thr), but TWO histogram copies per
// block: warps 0-3 -> copy 0, warps 4-7 -> copy 1. 16 copies/SM with no change
// to block count, flush traffic, or warps — isolates the contention variable.
__global__ __launch_bounds__(THREADS, 8)
void hist_kernel(const float* __restrict__ clean,
                 const float* __restrict__ pred,
                 const int* __restrict__ ids) {
    __shared__ unsigned long long sh[2 * NSEG];
    __shared__ int s_is_last;
    __shared__ float sbuf[8][8];

    const int tid = threadIdx.x;
    for (int i = tid; i < 2 * NSEG; i += THREADS) sh[i] = 0ull;
    __syncthreads();

    // ---------------- histogram phase ----------------
    const int b = blockIdx.y;
    const size_t base = (size_t)b * HW + (size_t)blockIdx.x * PIX_PER_BLOCK;
    const float4* __restrict__ c4 = (const float4*)(clean + base);
    const float4* __restrict__ p4 = (const float4*)(pred + base);
    const int4* __restrict__ i4 = (const int4*)(ids + base);

    // copy selector: threads 0-127 (warps 0-3) -> 0, threads 128-255 -> NSEG
    unsigned long long* mysh = sh + ((tid >> 7) ? NSEG : 0);

#pragma unroll
    for (int it = 0; it < VEC_ITERS; ++it) {
        const int idx = it * THREADS + tid;
        const float4 c = c4[idx];
        const float4 p = p4[idx];
        const int4 id = i4[idx];
        atomicAdd(&mysh[id.x], pack_pix(c.x, p.x));
        atomicAdd(&mysh[id.y], pack_pix(c.y, p.y));
        atomicAdd(&mysh[id.z], pack_pix(c.z, p.z));
        atomicAdd(&mysh[id.w], pack_pix(c.w, p.w));
    }
    __syncthreads();

    unsigned long long* gh = g_hist + (size_t)b * NSEG;
    for (int i = tid; i < NSEG; i += THREADS) {
        unsigned long long v = sh[i] + sh[NSEG + i];
        if (v) atomicAdd(&gh[i], v);
    }
    __syncthreads();

    // ---------------- per-batch last-block election ----------------
    if (tid == 0) {
        __threadfence();
        unsigned int old = atomicAdd(&g_ticket[b], 1u);
        s_is_last = (old == BLOCKS_PER_BATCH - 1) ? 1 : 0;
    }
    __syncthreads();
    if (!s_is_last) return;
    __threadfence();

    // ------- per-batch reduction tail (8 elected blocks run in parallel) ----
    const int lane = tid & 31;
    const int warp = tid >> 5;

    float acc[8];
#pragma unroll
    for (int q = 0; q < 8; ++q) acc[q] = 0.f;

#pragma unroll
    for (int it = 0; it < 2; ++it) {
        const int seg = 1 + it * 256 + tid;
        const unsigned long long v = __ldcg(&gh[seg]);

        const float cntf = (float)(unsigned int)(v >> CNT_SHIFT);
        const float inv = 1.0f / fmaxf(cntf, 1.0f);
        const float cm =
            (float)(unsigned int)((v >> CLEAN_SHIFT) & FIELD_MASK) * (1.0f / Q_SCALE) * inv;
        const float pm =
            (float)(unsigned int)(v & FIELD_MASK) * (1.0f / Q_SCALE) * inv;

        const bool valid = cntf >= 8.0f;
        const bool tumor = valid && (cm >= 0.7f);
        const bool normal = valid && (cm <= 0.3f);
        const bool enh = tumor || normal;
        const bool pres = valid && !enh;

        float target = cm;
        if (tumor) target = fminf(cm + 0.08f, 1.0f);
        if (normal) target = fmaxf(cm - 0.08f, 0.0f);
        const float d = pm - target;
        const float ad = fabsf(d);
        const float sl = (ad < 1.0f) ? 0.5f * d * d : ad - 0.5f;

        const bool tm = valid && (pm > 0.5f);
        const bool nm = valid && !(pm > 0.5f);

        acc[0] += enh ? sl : 0.f;
        acc[1] += enh ? 1.f : 0.f;
        acc[2] += pres ? sl : 0.f;
        acc[3] += pres ? 1.f : 0.f;
        acc[4] += tm ? pm : 0.f;
        acc[5] += tm ? 1.f : 0.f;
        acc[6] += nm ? pm : 0.f;
        acc[7] += nm ? 1.f : 0.f;
    }

#pragma unroll
    for (int q = 0; q < 8; ++q) {
        float x = acc[q];
#pragma unroll
        for (int o = 16; o > 0; o >>= 1) x += __shfl_down_sync(0xffffffffu, x, o);
        if (lane == 0) sbuf[warp][q] = x;
    }
    __syncthreads();

    // zero this batch's hist slice for the next invocation (overlaps tid0 work)
    for (int i = tid; i < NSEG; i += THREADS) gh[i] = 0ull;

    if (tid == 0) {
        float r[8];
#pragma unroll
        for (int q = 0; q < 8; ++q) r[q] = 0.f;
        for (int w = 0; w < 8; ++w)
#pragma unroll
            for (int q = 0; q < 8; ++q) r[q] += sbuf[w][q];

        const float loss_enh = r[0] / fmaxf(r[1], 1.0f);
        const float loss_pres = r[2] / fmaxf(r[3], 1.0f);
        const float has_e = (r[1] > 0.f) ? 1.f : 0.f;
        const float has_p = (r[3] > 0.f) ? 1.f : 0.f;
        const float cnt = has_e + has_p;
        const float loss_b =
            (loss_enh * has_e + 0.5f * loss_pres * has_p) / fmaxf(cnt, 1.0f);
        const float valid_b = (cnt > 0.f) ? 1.f : 0.f;

        const float has_t = (r[5] > 0.f) ? 1.f : 0.f;
        const float t_term = (r[4] / fmaxf(r[5], 1.0f)) * has_t;
        const float has_n = (r[7] > 0.f) ? 1.f : 0.f;
        const float n_term = (r[6] / fmaxf(r[7], 1.0f)) * has_n;

        g_partial[b][0] = loss_b * valid_b;
        g_partial[b][1] = valid_b;
        g_partial[b][2] = t_term;
        g_partial[b][3] = has_t;
        g_partial[b][4] = n_term;
        g_partial[b][5] = has_n;

        g_ticket[b] = 0u;
    }
}

// One warp: lane l < 8 combines batch l's partials; shuffle-reduce; write out.
__global__ __launch_bounds__(32)
void combine_kernel(float* __restrict__ out) {
    const int lane = threadIdx.x;

    float loss_term = 0.f, valid_b = 0.f, t_term = 0.f, has_t = 0.f,
          n_term = 0.f, has_n = 0.f;
    if (lane < 8) {
        loss_term = __ldcg(&g_partial[lane][0]);
        valid_b = __ldcg(&g_partial[lane][1]);
        t_term = __ldcg(&g_partial[lane][2]);
        has_t = __ldcg(&g_partial[lane][3]);
        n_term = __ldcg(&g_partial[lane][4]);
        has_n = __ldcg(&g_partial[lane][5]);
    }

#pragma unroll
    for (int o = 4; o > 0; o >>= 1) {
        loss_term += __shfl_down_sync(0xffffffffu, loss_term, o);
        valid_b += __shfl_down_sync(0xffffffffu, valid_b, o);
        t_term += __shfl_down_sync(0xffffffffu, t_term, o);
        has_t += __shfl_down_sync(0xffffffffu, has_t, o);
        n_term += __shfl_down_sync(0xffffffffu, n_term, o);
        has_n += __shfl_down_sync(0xffffffffu, has_n, o);
    }

    if (lane == 0) {
        float loss_prob = loss_term / fmaxf(valid_b, 1.0f);
        float avg_t = (has_t > 0.f) ? (t_term / fmaxf(has_t, 1.0f)) : -1.0f;
        float avg_n = (has_n > 0.f) ? (n_term / fmaxf(has_n, 1.0f)) : -1.0f;
        if (!(valid_b > 0.f)) {
            loss_prob = 0.0f;
            avg_t = -1.0f;
            avg_n = -1.0f;
        }
        out[0] = loss_prob;
        out[1] = 0.0f;
        out[2] = avg_t;
        out[3] = avg_n;
    }

    // re-zero g_partial (48 floats) for the next invocation
    float* gp = &g_partial[0][0];
    for (int i = lane; i < NBATCH * 6; i += 32) gp[i] = 0.f;
}

extern "C" void kernel_launch(void* const* d_in, const int* in_sizes, int n_in,
                              void* d_out, int out_size) {
    const float* clean = (const float*)d_in[0];
    const float* pred = (const float*)d_in[1];
    const int* ids = (const int*)d_in[2];
    float* out = (float*)d_out;

    dim3 grid(BLOCKS_PER_BATCH, NBATCH);
    hist_kernel<<<grid, THREADS>>>(clean, pred, ids);
    combine_kernel<<<1, 32>>>(out);
}

// round 17
// speedup vs baseline: 1.2319x; 1.0063x over previous
#include <cuda_runtime.h>
#include <cstdint>

// Problem constants
#define NSEG 513
#define NBATCH 8
#define HW (1024 * 1024)

#define BLOCKS_PER_BATCH 128
#define THREADS 256
#define PIX_PER_BLOCK (HW / BLOCKS_PER_BATCH)      // 8192
#define VEC_ITERS (PIX_PER_BLOCK / (THREADS * 4))  // 8

// Fixed-point packing: [count:12 | clean_q14:26 | pred_q14:26]
#define Q_SCALE 16384.0f
#define FIELD_MASK 0x3FFFFFFull
#define CNT_SHIFT 52
#define CLEAN_SHIFT 26

// Magic-number float->int: fmaf(x, 16384, 1.5*2^23) rounds x*16384 to the
// nearest integer (round-to-nearest-even, bit-identical to __float2uint_rn
// since x*16384 is exact and ulp(1.5*2^23)=1). Integer = low mantissa bits.
#define MAGIC 12582912.0f  // 1.5 * 2^23

// Global scratch — zero-initialized at module load; each invocation restores all
// of it to zero before finishing (elected blocks zero g_hist + tickets), so the
// correctness run and every graph replay observe zeros on entry.
__device__ unsigned long long g_hist[NBATCH * NSEG];
__device__ unsigned int g_ticket[NBATCH];
__device__ float g_partial[NBATCH][6];

__device__ __forceinline__ unsigned long long pack_pix(float c, float p) {
    // FFMA + AND per value instead of FMUL + F2I (slow-pipe conversion)
    unsigned int ci = __float_as_uint(fmaf(c, Q_SCALE, MAGIC)) & 0x3FFFFFu;
    unsigned int pi = __float_as_uint(fmaf(p, Q_SCALE, MAGIC)) & 0x3FFFFFu;
    return (unsigned long long)ci * (1ull << CLEAN_SHIFT) +
           ((1ull << CNT_SHIFT) + (unsigned long long)pi);
}

// R9 geometry exactly: 8 blocks/SM x 256 threads, single histogram copy.
__global__ __launch_bounds__(THREADS, 8)
void hist_kernel(const float* __restrict__ clean,
                 const float* __restrict__ pred,
                 const int* __restrict__ ids) {
    __shared__ unsigned long long sh[NSEG];
    __shared__ int s_is_last;
    __shared__ float sbuf[8][8];

    const int tid = threadIdx.x;
    for (int i = tid; i < NSEG; i += THREADS) sh[i] = 0ull;
    __syncthreads();

    // ---------------- histogram phase ----------------
    const int b = blockIdx.y;
    const size_t base = (size_t)b * HW + (size_t)blockIdx.x * PIX_PER_BLOCK;
    const float4* __restrict__ c4 = (const float4*)(clean + base);
    const float4* __restrict__ p4 = (const float4*)(pred + base);
    const int4* __restrict__ i4 = (const int4*)(ids + base);

#pragma unroll
    for (int it = 0; it < VEC_ITERS; ++it) {
        const int idx = it * THREADS + tid;
        const float4 c = c4[idx];
        const float4 p = p4[idx];
        const int4 id = i4[idx];
        atomicAdd(&sh[id.x], pack_pix(c.x, p.x));
        atomicAdd(&sh[id.y], pack_pix(c.y, p.y));
        atomicAdd(&sh[id.z], pack_pix(c.z, p.z));
        atomicAdd(&sh[id.w], pack_pix(c.w, p.w));
    }
    __syncthreads();

    unsigned long long* gh = g_hist + (size_t)b * NSEG;
    for (int i = tid; i < NSEG; i += THREADS) {
        unsigned long long v = sh[i];
        if (v) atomicAdd(&gh[i], v);
    }
    __syncthreads();

    // ---------------- per-batch last-block election ----------------
    if (tid == 0) {
        __threadfence();
        unsigned int old = atomicAdd(&g_ticket[b], 1u);
        s_is_last = (old == BLOCKS_PER_BATCH - 1) ? 1 : 0;
    }
    __syncthreads();
    if (!s_is_last) return;
    __threadfence();

    // ------- per-batch reduction tail (8 elected blocks run in parallel) ----
    const int lane = tid & 31;
    const int warp = tid >> 5;

    float acc[8];
#pragma unroll
    for (int q = 0; q < 8; ++q) acc[q] = 0.f;

#pragma unroll
    for (int it = 0; it < 2; ++it) {
        const int seg = 1 + it * 256 + tid;
        const unsigned long long v = __ldcg(&gh[seg]);

        const float cntf = (float)(unsigned int)(v >> CNT_SHIFT);
        const float inv = 1.0f / fmaxf(cntf, 1.0f);
        const float cm =
            (float)(unsigned int)((v >> CLEAN_SHIFT) & FIELD_MASK) * (1.0f / Q_SCALE) * inv;
        const float pm =
            (float)(unsigned int)(v & FIELD_MASK) * (1.0f / Q_SCALE) * inv;

        const bool valid = cntf >= 8.0f;
        const bool tumor = valid && (cm >= 0.7f);
        const bool normal = valid && (cm <= 0.3f);
        const bool enh = tumor || normal;
        const bool pres = valid && !enh;

        float target = cm;
        if (tumor) target = fminf(cm + 0.08f, 1.0f);
        if (normal) target = fmaxf(cm - 0.08f, 0.0f);
        const float d = pm - target;
        const float ad = fabsf(d);
        const float sl = (ad < 1.0f) ? 0.5f * d * d : ad - 0.5f;

        const bool tm = valid && (pm > 0.5f);
        const bool nm = valid && !(pm > 0.5f);

        acc[0] += enh ? sl : 0.f;
        acc[1] += enh ? 1.f : 0.f;
        acc[2] += pres ? sl : 0.f;
        acc[3] += pres ? 1.f : 0.f;
        acc[4] += tm ? pm : 0.f;
        acc[5] += tm ? 1.f : 0.f;
        acc[6] += nm ? pm : 0.f;
        acc[7] += nm ? 1.f : 0.f;
    }

#pragma unroll
    for (int q = 0; q < 8; ++q) {
        float x = acc[q];
#pragma unroll
        for (int o = 16; o > 0; o >>= 1) x += __shfl_down_sync(0xffffffffu, x, o);
        if (lane == 0) sbuf[warp][q] = x;
    }
    __syncthreads();

    // zero this batch's hist slice for the next invocation (overlaps tid0 work)
    for (int i = tid; i < NSEG; i += THREADS) gh[i] = 0ull;

    if (tid == 0) {
        float r[8];
#pragma unroll
        for (int q = 0; q < 8; ++q) r[q] = 0.f;
        for (int w = 0; w < 8; ++w)
#pragma unroll
            for (int q = 0; q < 8; ++q) r[q] += sbuf[w][q];

        const float loss_enh = r[0] / fmaxf(r[1], 1.0f);
        const float loss_pres = r[2] / fmaxf(r[3], 1.0f);
        const float has_e = (r[1] > 0.f) ? 1.f : 0.f;
        const float has_p = (r[3] > 0.f) ? 1.f : 0.f;
        const float cnt = has_e + has_p;
        const float loss_b =
            (loss_enh * has_e + 0.5f * loss_pres * has_p) / fmaxf(cnt, 1.0f);
        const float valid_b = (cnt > 0.f) ? 1.f : 0.f;

        const float has_t = (r[5] > 0.f) ? 1.f : 0.f;
        const float t_term = (r[4] / fmaxf(r[5], 1.0f)) * has_t;
        const float has_n = (r[7] > 0.f) ? 1.f : 0.f;
        const float n_term = (r[6] / fmaxf(r[7], 1.0f)) * has_n;

        g_partial[b][0] = loss_b * valid_b;
        g_partial[b][1] = valid_b;
        g_partial[b][2] = t_term;
        g_partial[b][3] = has_t;
        g_partial[b][4] = n_term;
        g_partial[b][5] = has_n;

        g_ticket[b] = 0u;
    }
}

// One warp: lane l < 8 combines batch l's partials; shuffle-reduce; write out.
__global__ __launch_bounds__(32)
void combine_kernel(float* __restrict__ out) {
    const int lane = threadIdx.x;

    float loss_term = 0.f, valid_b = 0.f, t_term = 0.f, has_t = 0.f,
          n_term = 0.f, has_n = 0.f;
    if (lane < 8) {
        loss_term = __ldcg(&g_partial[lane][0]);
        valid_b = __ldcg(&g_partial[lane][1]);
        t_term = __ldcg(&g_partial[lane][2]);
        has_t = __ldcg(&g_partial[lane][3]);
        n_term = __ldcg(&g_partial[lane][4]);
        has_n = __ldcg(&g_partial[lane][5]);
    }

#pragma unroll
    for (int o = 4; o > 0; o >>= 1) {
        loss_term += __shfl_down_sync(0xffffffffu, loss_term, o);
        valid_b += __shfl_down_sync(0xffffffffu, valid_b, o);
        t_term += __shfl_down_sync(0xffffffffu, t_term, o);
        has_t += __shfl_down_sync(0xffffffffu, has_t, o);
        n_term += __shfl_down_sync(0xffffffffu, n_term, o);
        has_n += __shfl_down_sync(0xffffffffu, has_n, o);
    }

    if (lane == 0) {
        float loss_prob = loss_term / fmaxf(valid_b, 1.0f);
        float avg_t = (has_t > 0.f) ? (t_term / fmaxf(has_t, 1.0f)) : -1.0f;
        float avg_n = (has_n > 0.f) ? (n_term / fmaxf(has_n, 1.0f)) : -1.0f;
        if (!(valid_b > 0.f)) {
            loss_prob = 0.0f;
            avg_t = -1.0f;
            avg_n = -1.0f;
        }
        out[0] = loss_prob;
        out[1] = 0.0f;
        out[2] = avg_t;
        out[3] = avg_n;
    }

    // re-zero g_partial (48 floats) for the next invocation
    float* gp = &g_partial[0][0];
    for (int i = lane; i < NBATCH * 6; i += 32) gp[i] = 0.f;
}

extern "C" void kernel_launch(void* const* d_in, const int* in_sizes, int n_in,
                              void* d_out, int out_size) {
    const float* clean = (const float*)d_in[0];
    const float* pred = (const float*)d_in[1];
    const int* ids = (const int*)d_in[2];
    float* out = (float*)d_out;

    dim3 grid(BLOCKS_PER_BATCH, NBATCH);
    hist_kernel<<<grid, THREADS>>>(clean, pred, ids);
    combine_kernel<<<1, 32>>>(out);
}